// round 12
// baseline (speedup 1.0000x reference)
#include <cuda_runtime.h>

#define NG 1024
#define R0 8192
#define C0 4096
#define R1 4096
#define C1 2048
#define RM 512

#define GPB 8                   // groups per obsA block
#define A_BLOCKS 512            // (1024/8 group-sets) x (4096/1024 col tiles)
#define P1_BLOCKS 512           // theta1 rows / 8 rows-per-block
#define MAIN_BLOCKS (A_BLOCKS + P1_BLOCKS)   // 1024
#define TAIL_WORKERS 148        // last finishers do obs-B (one per SM, provably safe)
#define FIN_THRESH (MAIN_BLOCKS - TAIL_WORKERS)  // 876
#define C_BLOCKS 16
#define LCAP 256                // per-group row list capacity (mean cnt = 8)
#define FCAP 1024               // flat list capacity (actual total ~64)

// Scratch (device globals — zero at process start; restored to zero at the
// end of every call, so no zero-prologue kernel).
__device__ float  g_p2[C0];
__device__ float  g_p1[R1];
__device__ double g_loss[3];
__device__ int    g_p1_done;    // P1 producer blocks finished
__device__ int    g_fin;        // finish-order counter for k_main blocks
__device__ int    g_done;       // k_post finisher counter

__device__ __forceinline__ float block_reduce256(float v, float* sh) {
    int t = threadIdx.x;
    #pragma unroll
    for (int o = 16; o; o >>= 1) v += __shfl_down_sync(0xffffffffu, v, o);
    if ((t & 31) == 0) sh[t >> 5] = v;
    __syncthreads();
    if (t < 8) {
        v = sh[t];
        #pragma unroll
        for (int o = 4; o; o >>= 1) v += __shfl_down_sync(0x000000ffu, v, o);
    }
    return v; // valid in thread 0
}

// ---------------------------------------------------------------------------
// Main fused kernel. A-blocks / P1-blocks interleaved by bid parity; the last
// TAIL_WORKERS finishers additionally compute obs-B (mapping1 @ p1) after a
// provably-safe spin on the p1_done counter.
// ---------------------------------------------------------------------------
__global__ __launch_bounds__(256) void k_main(const float* __restrict__ theta0,
                                              const float* __restrict__ obs0,
                                              const float* __restrict__ theta1,
                                              const unsigned int* __restrict__ idx_raw,
                                              const float* __restrict__ mapping1,
                                              const float* __restrict__ obs1) {
    __shared__ float sh[8];
    __shared__ int s_fin;
    int bx = blockIdx.x;
    int t = threadIdx.x;

    if ((bx & 1) == 0) {
        // ----------------- obs-A -----------------
        int ab = bx >> 1;               // 0..511
        __shared__ int   scnt[GPB];
        __shared__ short slist[GPB * LCAP];
        __shared__ short sflat[FCAP];
        int gset = ab >> 2;             // 0..127
        int tile = ab & 3;              // 0..3
        int g0 = gset * GPB;
        int c = tile * 1024 + t * 4;

        if (t < GPB) scnt[t] = 0;
        __syncthreads();

        // int64 vs int32 width detection: for int64 values < 1024 every odd
        // 32-bit word is zero; for int32 odd words are random group ids.
        unsigned int hi = 0;
        #pragma unroll
        for (int s = 0; s < 4; s++) hi |= idx_raw[2 * (t + 256 * s) + 1];
        int is32 = __syncthreads_or(hi != 0u);

        // Scan idx, collect rows belonging to our 8 groups.
        if (is32) {
            const int* p = (const int*)idx_raw;
            #pragma unroll 4
            for (int i = t; i < R0; i += 256) {
                int g = p[i] - g0;
                if ((unsigned)g < GPB) {
                    int s = atomicAdd(&scnt[g], 1);
                    if (s < LCAP) slist[g * LCAP + s] = (short)i;
                }
            }
        } else {
            const long long* p = (const long long*)idx_raw;
            #pragma unroll 4
            for (int i = t; i < R0; i += 256) {
                int g = (int)p[i] - g0;
                if ((unsigned)g < GPB) {
                    int s = atomicAdd(&scnt[g], 1);
                    if (s < LCAP) slist[g * LCAP + s] = (short)i;
                }
            }
        }
        __syncthreads();

        // block-uniform prefix over 8 group counts
        int soff[GPB + 1];
        {
            int acc = 0;
            #pragma unroll
            for (int g = 0; g < GPB; g++) {
                soff[g] = acc;
                int cg = scnt[g];
                if (cg > LCAP) cg = LCAP;
                acc += cg;
                if (acc > FCAP) acc = FCAP;
            }
            soff[GPB] = acc;
        }
        // compact into flat ordered list
        #pragma unroll
        for (int g = 0; g < GPB; g++) {
            int cg = soff[g + 1] - soff[g];
            for (int s = t; s < cg; s += 256)
                sflat[soff[g] + s] = slist[g * LCAP + s];
        }
        __syncthreads();

        int total = soff[GPB];
        int gg = 0;
        int bnd = soff[1];
        float ax = 0.f, ay = 0.f, az = 0.f, aw = 0.f;   // current group sum
        float px = 0.f, py = 0.f, pz = 0.f, pw = 0.f;   // p2 partial (8 groups)
        float lsum = 0.f;                                // loss_a partial
        // prefetch obs0 of group 0; at each flush we consume it and prefetch
        // the next group's, hiding the load under the next group's gather.
        float4 oc = *(const float4*)(obs0 + (size_t)g0 * C0 + c);

#define FLUSH_GROUP() do {                                                   \
            float dx_ = oc.x - ax, dy_ = oc.y - ay;                          \
            float dz_ = oc.z - az, dw_ = oc.w - aw;                          \
            lsum += dx_ * dx_ + dy_ * dy_ + dz_ * dz_ + dw_ * dw_;           \
            px += ax; py += ay; pz += az; pw += aw;                          \
            ax = ay = az = aw = 0.f;                                         \
        } while (0)

        for (int base = 0; base < total; base += 8) {
            float4 v[8];
            #pragma unroll
            for (int k = 0; k < 8; k++) {
                int idx = base + k;
                if (idx < total) {
                    int r = (unsigned short)sflat[idx];
                    v[k] = *(const float4*)(theta0 + (size_t)r * C0 + c);
                }
            }
            #pragma unroll
            for (int k = 0; k < 8; k++) {
                int idx = base + k;
                if (idx < total) {
                    while (idx == bnd) {
                        FLUSH_GROUP();
                        gg++;
                        bnd = soff[gg + 1];
                        oc = *(const float4*)(obs0 + (size_t)(g0 + gg) * C0 + c);
                    }
                    ax += __expf(v[k].x); ay += __expf(v[k].y);
                    az += __expf(v[k].z); aw += __expf(v[k].w);
                }
            }
        }
        while (gg < GPB) {
            FLUSH_GROUP();
            gg++;
            if (gg < GPB)
                oc = *(const float4*)(obs0 + (size_t)(g0 + gg) * C0 + c);
        }
#undef FLUSH_GROUP

        atomicAdd(&g_p2[c + 0], px);
        atomicAdd(&g_p2[c + 1], py);
        atomicAdd(&g_p2[c + 2], pz);
        atomicAdd(&g_p2[c + 3], pw);

        float v = block_reduce256(lsum, sh);
        if (t == 0) atomicAdd(&g_loss[0], (double)v);
    } else {
        // ----------------- p1 rowsum-of-exp: one warp per theta1 row -------
        int gid = (bx >> 1) * 256 + t;
        int w = gid >> 5, lane = gid & 31;
        const float4* row = (const float4*)(theta1 + (size_t)w * C1);
        float s = 0.f;
        #pragma unroll 4
        for (int j = lane; j < C1 / 4; j += 32) {
            float4 v = row[j];
            s += __expf(v.x) + __expf(v.y) + __expf(v.z) + __expf(v.w);
        }
        #pragma unroll
        for (int o = 16; o; o >>= 1) s += __shfl_down_sync(0xffffffffu, s, o);
        if (lane == 0) g_p1[w] = s;
        __syncthreads();
        if (t == 0) {
            __threadfence();
            atomicAdd(&g_p1_done, 1);
        }
    }

    // --------- finish-order tail: last TAIL_WORKERS finishers do obs-B ------
    __syncthreads();
    if (t == 0) s_fin = atomicAdd(&g_fin, 1);
    __syncthreads();
    int fin = s_fin;
    if (fin >= FIN_THRESH) {
        int tau = fin - FIN_THRESH;     // 0..147
        if (t == 0) {
            // All 1024 blocks are dispatched once 876 finished (capacity>=148),
            // so every P1 block is resident or done -> bounded spin.
            while (*(volatile int*)&g_p1_done < P1_BLOCKS) __nanosleep(64);
        }
        __syncthreads();
        __threadfence();
        const float4* p = (const float4*)g_p1;
        for (int w = tau; w < RM; w += TAIL_WORKERS) {
            const float4* m = (const float4*)(mapping1 + (size_t)w * C0);
            float s = 0.f;
            #pragma unroll
            for (int j = 0; j < 4; j++) {
                int k = t + j * 256;
                float4 a = m[k];
                float4 q = __ldcg(&p[k]);   // bypass L1: freshly produced
                s += a.x * q.x + a.y * q.y + a.z * q.z + a.w * q.w;
            }
            float r = block_reduce256(s, sh);
            if (t == 0) {
                double d = (double)obs1[w] - (double)r;
                atomicAdd(&g_loss[1], d * d);
            }
            __syncthreads();
        }
    }
}

// ---------------------------------------------------------------------------
// Tiny epilogue: obs-C (16 blocks) + final scalar + state restore.
// Kernel boundary guarantees all k_main writes (g_p2, g_loss[0], g_loss[1])
// are visible.
// ---------------------------------------------------------------------------
__global__ __launch_bounds__(256) void k_post(const float* __restrict__ obs2,
                                              float* __restrict__ out) {
    __shared__ float sh[8];
    int bx = blockIdx.x;
    int t = threadIdx.x;
    int c = bx * 256 + t;
    float d = obs2[c] - g_p2[c];
    g_p2[c] = 0.f;                      // restore for next call
    float v = block_reduce256(d * d, sh);
    if (t == 0) atomicAdd(&g_loss[2], (double)v);
    __threadfence();
    if (t == 0) {
        int done = atomicAdd(&g_done, 1);
        if (done == (int)gridDim.x - 1) {
            __threadfence();
            double la = *(volatile double*)&g_loss[0];
            double lb = *(volatile double*)&g_loss[1];
            double lc = *(volatile double*)&g_loss[2];
            la /= (double)((size_t)NG * (size_t)C0);
            lb /= (double)RM;
            lc = 0.5 * lc / (double)C0;
            out[0] = (float)((la + lb + lc) / 3.0);
            g_loss[0] = 0.0; g_loss[1] = 0.0; g_loss[2] = 0.0;
            g_p1_done = 0; g_fin = 0; g_done = 0;
        }
    }
}

extern "C" void kernel_launch(void* const* d_in, const int* in_sizes, int n_in,
                              void* d_out, int out_size) {
    const float* theta0   = (const float*)d_in[0];
    const float* theta1   = (const float*)d_in[1];
    const float* obs0     = (const float*)d_in[2];
    const float* obs1     = (const float*)d_in[3];
    const float* obs2     = (const float*)d_in[4];
    const void*  idx0     = d_in[5];
    const float* mapping1 = (const float*)d_in[6];
    float* out = (float*)d_out;

    k_main<<<MAIN_BLOCKS, 256>>>(theta0, obs0, theta1,
                                 (const unsigned int*)idx0, mapping1, obs1);
    k_post<<<C_BLOCKS, 256>>>(obs2, out);
}

// round 13
// speedup vs baseline: 1.2353x; 1.2353x over previous
#include <cuda_runtime.h>

#define NG 1024
#define R0 8192
#define C0 4096
#define R1 4096
#define C1 2048
#define RM 512

#define GPB 8                   // groups per obsA block
#define A_BLOCKS 512            // (1024/8 group-sets) x (4096/1024 col tiles)
#define P1_BLOCKS 512           // theta1 rows / 8 rows-per-block
#define MAIN_BLOCKS (A_BLOCKS + P1_BLOCKS)       // 1024
#define TAIL_WORKERS 148        // last finishers do obs-B/obs-C (provably safe)
#define FIN_THRESH (MAIN_BLOCKS - TAIL_WORKERS)  // 876
#define LCAP 256                // per-group row list capacity (mean cnt = 8)
#define FCAP 1024               // flat list capacity (actual total ~64)

// Scratch (device globals — zero at process start; restored to zero at the
// end of every call, so no zero-prologue kernel).
__device__ float  g_p2[C0];
__device__ float  g_p1[R1];
__device__ double g_loss[3];
__device__ int    g_a_done;     // A-blocks finished (p2 complete)
__device__ int    g_p1_done;    // P1 blocks finished
__device__ int    g_fin;        // finish-order counter
__device__ int    g_done;       // absolute-last counter

__device__ __forceinline__ float block_reduce256(float v, float* sh) {
    int t = threadIdx.x;
    #pragma unroll
    for (int o = 16; o; o >>= 1) v += __shfl_down_sync(0xffffffffu, v, o);
    if ((t & 31) == 0) sh[t >> 5] = v;
    __syncthreads();
    if (t < 8) {
        v = sh[t];
        #pragma unroll
        for (int o = 4; o; o >>= 1) v += __shfl_down_sync(0x000000ffu, v, o);
    }
    return v; // valid in thread 0
}

// ---------------------------------------------------------------------------
// Single fused kernel. A-blocks / P1-blocks interleaved by bid parity
// (R8 inner loops, unmodified). Finish-order tail: the last TAIL_WORKERS
// finishers compute obs-B; tail worker 0 also computes obs-C; the absolute
// last block writes the final scalar and restores all state.
// ---------------------------------------------------------------------------
__global__ __launch_bounds__(256) void k_all(const float* __restrict__ theta0,
                                             const float* __restrict__ obs0,
                                             const float* __restrict__ theta1,
                                             const unsigned int* __restrict__ idx_raw,
                                             const float* __restrict__ mapping1,
                                             const float* __restrict__ obs1,
                                             const float* __restrict__ obs2,
                                             float* __restrict__ out) {
    __shared__ float sh[8];
    __shared__ int s_fin;
    int bx = blockIdx.x;
    int t = threadIdx.x;

    if ((bx & 1) == 0) {
        // ----------------- obs-A (R8 exact) -----------------
        int ab = bx >> 1;               // 0..511
        __shared__ int   scnt[GPB];
        __shared__ short slist[GPB * LCAP];
        __shared__ short sflat[FCAP];
        int gset = ab >> 2;             // 0..127
        int tile = ab & 3;              // 0..3
        int g0 = gset * GPB;
        int c = tile * 1024 + t * 4;

        if (t < GPB) scnt[t] = 0;
        __syncthreads();

        // int64 vs int32 width detection: for int64 values < 1024 every odd
        // 32-bit word is zero; for int32 odd words are random group ids.
        unsigned int hi = 0;
        #pragma unroll
        for (int s = 0; s < 4; s++) hi |= idx_raw[2 * (t + 256 * s) + 1];
        int is32 = __syncthreads_or(hi != 0u);

        if (is32) {
            const int* p = (const int*)idx_raw;
            #pragma unroll 4
            for (int i = t; i < R0; i += 256) {
                int g = p[i] - g0;
                if ((unsigned)g < GPB) {
                    int s = atomicAdd(&scnt[g], 1);
                    if (s < LCAP) slist[g * LCAP + s] = (short)i;
                }
            }
        } else {
            const long long* p = (const long long*)idx_raw;
            #pragma unroll 4
            for (int i = t; i < R0; i += 256) {
                int g = (int)p[i] - g0;
                if ((unsigned)g < GPB) {
                    int s = atomicAdd(&scnt[g], 1);
                    if (s < LCAP) slist[g * LCAP + s] = (short)i;
                }
            }
        }
        __syncthreads();

        int soff[GPB + 1];
        {
            int acc = 0;
            #pragma unroll
            for (int g = 0; g < GPB; g++) {
                soff[g] = acc;
                int cg = scnt[g];
                if (cg > LCAP) cg = LCAP;
                acc += cg;
                if (acc > FCAP) acc = FCAP;
            }
            soff[GPB] = acc;
        }
        #pragma unroll
        for (int g = 0; g < GPB; g++) {
            int cg = soff[g + 1] - soff[g];
            for (int s = t; s < cg; s += 256)
                sflat[soff[g] + s] = slist[g * LCAP + s];
        }
        __syncthreads();

        int total = soff[GPB];
        int gg = 0;
        int bnd = soff[1];
        float ax = 0.f, ay = 0.f, az = 0.f, aw = 0.f;
        float px = 0.f, py = 0.f, pz = 0.f, pw = 0.f;
        float lsum = 0.f;

#define FLUSH_GROUP() do {                                                   \
            float4 o_ = *(const float4*)(obs0 + (size_t)(g0 + gg) * C0 + c); \
            float dx_ = o_.x - ax, dy_ = o_.y - ay;                          \
            float dz_ = o_.z - az, dw_ = o_.w - aw;                          \
            lsum += dx_ * dx_ + dy_ * dy_ + dz_ * dz_ + dw_ * dw_;           \
            px += ax; py += ay; pz += az; pw += aw;                          \
            ax = ay = az = aw = 0.f;                                         \
        } while (0)

        for (int base = 0; base < total; base += 8) {
            float4 v[8];
            #pragma unroll
            for (int k = 0; k < 8; k++) {
                int idx = base + k;
                if (idx < total) {
                    int r = (unsigned short)sflat[idx];
                    v[k] = *(const float4*)(theta0 + (size_t)r * C0 + c);
                }
            }
            #pragma unroll
            for (int k = 0; k < 8; k++) {
                int idx = base + k;
                if (idx < total) {
                    while (idx == bnd) { FLUSH_GROUP(); gg++; bnd = soff[gg + 1]; }
                    ax += __expf(v[k].x); ay += __expf(v[k].y);
                    az += __expf(v[k].z); aw += __expf(v[k].w);
                }
            }
        }
        while (gg < GPB) { FLUSH_GROUP(); gg++; }
#undef FLUSH_GROUP

        atomicAdd(&g_p2[c + 0], px);
        atomicAdd(&g_p2[c + 1], py);
        atomicAdd(&g_p2[c + 2], pz);
        atomicAdd(&g_p2[c + 3], pw);
        __threadfence();                 // order p2 atomics before a_done

        float v = block_reduce256(lsum, sh);
        if (t == 0) {
            atomicAdd(&g_loss[0], (double)v);
            atomicAdd(&g_a_done, 1);
        }
    } else {
        // ----------------- p1 rowsum-of-exp (R8 exact) -----------------
        int gid = (bx >> 1) * 256 + t;
        int w = gid >> 5, lane = gid & 31;
        const float4* row = (const float4*)(theta1 + (size_t)w * C1);
        float s = 0.f;
        #pragma unroll 4
        for (int j = lane; j < C1 / 4; j += 32) {
            float4 v = row[j];
            s += __expf(v.x) + __expf(v.y) + __expf(v.z) + __expf(v.w);
        }
        #pragma unroll
        for (int o = 16; o; o >>= 1) s += __shfl_down_sync(0xffffffffu, s, o);
        if (lane == 0) g_p1[w] = s;
        __threadfence();                 // order p1 stores before p1_done
        __syncthreads();
        if (t == 0) atomicAdd(&g_p1_done, 1);
    }

    // --------- finish-order tail ---------
    __syncthreads();
    if (t == 0) s_fin = atomicAdd(&g_fin, 1);
    __syncthreads();
    int fin = s_fin;
    if (fin >= FIN_THRESH) {
        int tau = fin - FIN_THRESH;     // 0..147
        // obs-B: gate on all P1 producers done. Safe: fin>=876 => all 1024
        // blocks dispatched (capacity >= 3/SM*148), P1 blocks independent.
        if (t == 0) {
            while (*(volatile int*)&g_p1_done < P1_BLOCKS) __nanosleep(64);
        }
        __syncthreads();
        __threadfence();
        const float4* p = (const float4*)g_p1;
        for (int w = tau; w < RM; w += TAIL_WORKERS) {
            const float4* m = (const float4*)(mapping1 + (size_t)w * C0);
            float s = 0.f;
            #pragma unroll
            for (int j = 0; j < 4; j++) {
                int k = t + j * 256;
                float4 a = m[k];
                float4 q = __ldcg(&p[k]);   // L2: freshly produced
                s += a.x * q.x + a.y * q.y + a.z * q.z + a.w * q.w;
            }
            float r = block_reduce256(s, sh);
            if (t == 0) {
                double d = (double)obs1[w] - (double)r;
                atomicAdd(&g_loss[1], d * d);
            }
            __syncthreads();
        }
        // obs-C: one tail worker, gated on all A-blocks' p2 atomics.
        if (tau == 0) {
            if (t == 0) {
                while (*(volatile int*)&g_a_done < A_BLOCKS) __nanosleep(64);
            }
            __syncthreads();
            __threadfence();
            float ls = 0.f;
            for (int i = t; i < C0; i += 256) {
                float pv = __ldcg(&g_p2[i]);   // L2: atomics land in L2
                float d = obs2[i] - pv;
                g_p2[i] = 0.f;                 // restore for next call
                ls += d * d;
            }
            float v = block_reduce256(ls, sh);
            if (t == 0) atomicAdd(&g_loss[2], (double)v);
        }
    }

    // --------- absolute last block writes the output ---------
    __syncthreads();
    if (t == 0) {
        __threadfence();
        int done = atomicAdd(&g_done, 1);
        if (done == MAIN_BLOCKS - 1) {
            __threadfence();
            double la = *(volatile double*)&g_loss[0];
            double lb = *(volatile double*)&g_loss[1];
            double lc = *(volatile double*)&g_loss[2];
            la /= (double)((size_t)NG * (size_t)C0);
            lb /= (double)RM;
            lc = 0.5 * lc / (double)C0;
            out[0] = (float)((la + lb + lc) / 3.0);
            g_loss[0] = 0.0; g_loss[1] = 0.0; g_loss[2] = 0.0;
            g_a_done = 0; g_p1_done = 0; g_fin = 0; g_done = 0;
        }
    }
}

extern "C" void kernel_launch(void* const* d_in, const int* in_sizes, int n_in,
                              void* d_out, int out_size) {
    const float* theta0   = (const float*)d_in[0];
    const float* theta1   = (const float*)d_in[1];
    const float* obs0     = (const float*)d_in[2];
    const float* obs1     = (const float*)d_in[3];
    const float* obs2     = (const float*)d_in[4];
    const void*  idx0     = d_in[5];
    const float* mapping1 = (const float*)d_in[6];
    float* out = (float*)d_out;

    k_all<<<MAIN_BLOCKS, 256>>>(theta0, obs0, theta1,
                                (const unsigned int*)idx0,
                                mapping1, obs1, obs2, out);
}

// round 14
// speedup vs baseline: 1.3758x; 1.1138x over previous
#include <cuda_runtime.h>

#define NG 1024
#define R0 8192
#define C0 4096
#define R1 4096
#define C1 2048
#define RM 512

#define GPB 8                   // groups per obsA block
#define A_BLOCKS 512            // (1024/8 group-sets) x (4096/1024 col tiles)
#define P1_BLOCKS 512           // theta1 rows / 8 rows-per-block
#define MAIN_BLOCKS (A_BLOCKS + P1_BLOCKS)       // 1024
#define TAIL_WORKERS 148        // last finishers do obs-B/obs-C (provably safe)
#define FIN_THRESH (MAIN_BLOCKS - TAIL_WORKERS)  // 876
#define LCAP 256                // per-group row list capacity (mean cnt = 8)
#define FCAP 1024               // flat list capacity (actual total ~64)

// Scratch (device globals — zero at process start; restored to zero at the
// end of every call, so no zero-prologue kernel).
__device__ float  g_p2[C0];
__device__ float  g_p1[R1];
__device__ double g_loss[3];
__device__ int    g_a_done;     // A-blocks finished (p2 complete)
__device__ int    g_p1_done;    // P1 blocks finished
__device__ int    g_fin;        // finish-order counter
__device__ int    g_done;       // absolute-last counter

__device__ __forceinline__ float block_reduce256(float v, float* sh) {
    int t = threadIdx.x;
    #pragma unroll
    for (int o = 16; o; o >>= 1) v += __shfl_down_sync(0xffffffffu, v, o);
    if ((t & 31) == 0) sh[t >> 5] = v;
    __syncthreads();
    if (t < 8) {
        v = sh[t];
        #pragma unroll
        for (int o = 4; o; o >>= 1) v += __shfl_down_sync(0x000000ffu, v, o);
    }
    return v; // valid in thread 0
}

// ---------------------------------------------------------------------------
// Single fused kernel. A-blocks / P1-blocks interleaved by bid parity.
// A-path gather is software-pipelined (double-buffered 4+4): next batch's
// loads issue before current batch is consumed -> no inter-batch bubble.
// Finish-order tail: last TAIL_WORKERS finishers do obs-B; the first 16 of
// them also each do a 256-col slice of obs-C; absolute last block writes out.
// ---------------------------------------------------------------------------
__global__ __launch_bounds__(256) void k_all(const float* __restrict__ theta0,
                                             const float* __restrict__ obs0,
                                             const float* __restrict__ theta1,
                                             const unsigned int* __restrict__ idx_raw,
                                             const float* __restrict__ mapping1,
                                             const float* __restrict__ obs1,
                                             const float* __restrict__ obs2,
                                             float* __restrict__ out) {
    __shared__ float sh[8];
    __shared__ int s_fin;
    int bx = blockIdx.x;
    int t = threadIdx.x;

    if ((bx & 1) == 0) {
        // ----------------- obs-A -----------------
        int ab = bx >> 1;               // 0..511
        __shared__ int   scnt[GPB];
        __shared__ short slist[GPB * LCAP];
        __shared__ short sflat[FCAP];
        int gset = ab >> 2;             // 0..127
        int tile = ab & 3;              // 0..3
        int g0 = gset * GPB;
        int c = tile * 1024 + t * 4;

        if (t < GPB) scnt[t] = 0;
        __syncthreads();

        // int64 vs int32 width detection: for int64 values < 1024 every odd
        // 32-bit word is zero; for int32 odd words are random group ids.
        unsigned int hi = 0;
        #pragma unroll
        for (int s = 0; s < 4; s++) hi |= idx_raw[2 * (t + 256 * s) + 1];
        int is32 = __syncthreads_or(hi != 0u);

        if (is32) {
            const int* p = (const int*)idx_raw;
            #pragma unroll 4
            for (int i = t; i < R0; i += 256) {
                int g = p[i] - g0;
                if ((unsigned)g < GPB) {
                    int s = atomicAdd(&scnt[g], 1);
                    if (s < LCAP) slist[g * LCAP + s] = (short)i;
                }
            }
        } else {
            const long long* p = (const long long*)idx_raw;
            #pragma unroll 4
            for (int i = t; i < R0; i += 256) {
                int g = (int)p[i] - g0;
                if ((unsigned)g < GPB) {
                    int s = atomicAdd(&scnt[g], 1);
                    if (s < LCAP) slist[g * LCAP + s] = (short)i;
                }
            }
        }
        __syncthreads();

        int soff[GPB + 1];
        {
            int acc = 0;
            #pragma unroll
            for (int g = 0; g < GPB; g++) {
                soff[g] = acc;
                int cg = scnt[g];
                if (cg > LCAP) cg = LCAP;
                acc += cg;
                if (acc > FCAP) acc = FCAP;
            }
            soff[GPB] = acc;
        }
        #pragma unroll
        for (int g = 0; g < GPB; g++) {
            int cg = soff[g + 1] - soff[g];
            for (int s = t; s < cg; s += 256)
                sflat[soff[g] + s] = slist[g * LCAP + s];
        }
        __syncthreads();

        int total = soff[GPB];
        int gg = 0;
        int bnd = soff[1];
        float ax = 0.f, ay = 0.f, az = 0.f, aw = 0.f;
        float px = 0.f, py = 0.f, pz = 0.f, pw = 0.f;
        float lsum = 0.f;

#define FLUSH_GROUP() do {                                                   \
            float4 o_ = *(const float4*)(obs0 + (size_t)(g0 + gg) * C0 + c); \
            float dx_ = o_.x - ax, dy_ = o_.y - ay;                          \
            float dz_ = o_.z - az, dw_ = o_.w - aw;                          \
            lsum += dx_ * dx_ + dy_ * dy_ + dz_ * dz_ + dw_ * dw_;           \
            px += ax; py += ay; pz += az; pw += aw;                          \
            ax = ay = az = aw = 0.f;                                         \
        } while (0)

#define LDI(I) (((I) < total)                                                \
            ? *(const float4*)(theta0 +                                      \
                  (size_t)(unsigned short)sflat[(I)] * C0 + c)               \
            : make_float4(0.f, 0.f, 0.f, 0.f))

#define CONSUME(V, I)                                                        \
        if ((I) < total) {                                                   \
            int idx_ = (I);                                                  \
            while (idx_ == bnd) { FLUSH_GROUP(); gg++; bnd = soff[gg + 1]; } \
            ax += __expf(V.x); ay += __expf(V.y);                            \
            az += __expf(V.z); aw += __expf(V.w);                            \
        }

        // Double-buffered 4+4 pipeline: next batch's loads issue before the
        // current batch is consumed -> sustained MLP, no inter-batch bubble.
        float4 c0 = LDI(0), c1 = LDI(1), c2 = LDI(2), c3 = LDI(3);
        for (int base = 0; base < total; base += 4) {
            float4 n0 = LDI(base + 4), n1 = LDI(base + 5);
            float4 n2 = LDI(base + 6), n3 = LDI(base + 7);
            CONSUME(c0, base + 0) CONSUME(c1, base + 1)
            CONSUME(c2, base + 2) CONSUME(c3, base + 3)
            c0 = n0; c1 = n1; c2 = n2; c3 = n3;
        }
        while (gg < GPB) { FLUSH_GROUP(); gg++; }
#undef LDI
#undef CONSUME
#undef FLUSH_GROUP

        atomicAdd(&g_p2[c + 0], px);
        atomicAdd(&g_p2[c + 1], py);
        atomicAdd(&g_p2[c + 2], pz);
        atomicAdd(&g_p2[c + 3], pw);
        __threadfence();                 // order p2 atomics before a_done

        float v = block_reduce256(lsum, sh);
        if (t == 0) {
            atomicAdd(&g_loss[0], (double)v);
            atomicAdd(&g_a_done, 1);
        }
    } else {
        // ----------------- p1 rowsum-of-exp -----------------
        int gid = (bx >> 1) * 256 + t;
        int w = gid >> 5, lane = gid & 31;
        const float4* row = (const float4*)(theta1 + (size_t)w * C1);
        float s = 0.f;
        #pragma unroll 4
        for (int j = lane; j < C1 / 4; j += 32) {
            float4 v = row[j];
            s += __expf(v.x) + __expf(v.y) + __expf(v.z) + __expf(v.w);
        }
        #pragma unroll
        for (int o = 16; o; o >>= 1) s += __shfl_down_sync(0xffffffffu, s, o);
        if (lane == 0) g_p1[w] = s;
        __threadfence();                 // order p1 stores before p1_done
        __syncthreads();
        if (t == 0) atomicAdd(&g_p1_done, 1);
    }

    // --------- finish-order tail ---------
    __syncthreads();
    if (t == 0) s_fin = atomicAdd(&g_fin, 1);
    __syncthreads();
    int fin = s_fin;
    if (fin >= FIN_THRESH) {
        int tau = fin - FIN_THRESH;     // 0..147
        // obs-B: gate on all P1 producers done. Safe: fin>=876 => all 1024
        // blocks dispatched (capacity >= 4/SM*148), P1 blocks independent.
        if (t == 0) {
            while (*(volatile int*)&g_p1_done < P1_BLOCKS) __nanosleep(64);
        }
        __syncthreads();
        __threadfence();
        const float4* p = (const float4*)g_p1;
        for (int w = tau; w < RM; w += TAIL_WORKERS) {
            const float4* m = (const float4*)(mapping1 + (size_t)w * C0);
            float s = 0.f;
            #pragma unroll
            for (int j = 0; j < 4; j++) {
                int k = t + j * 256;
                float4 a = m[k];
                float4 q = __ldcg(&p[k]);   // L2: freshly produced
                s += a.x * q.x + a.y * q.y + a.z * q.z + a.w * q.w;
            }
            float r = block_reduce256(s, sh);
            if (t == 0) {
                double d = (double)obs1[w] - (double)r;
                atomicAdd(&g_loss[1], d * d);
            }
            __syncthreads();
        }
        // obs-C: first 16 tail workers each take a 256-col slice, gated on
        // all A-blocks' p2 atomics being complete.
        if (tau < 16) {
            if (t == 0) {
                while (*(volatile int*)&g_a_done < A_BLOCKS) __nanosleep(64);
            }
            __syncthreads();
            __threadfence();
            int i = tau * 256 + t;
            float pv = __ldcg(&g_p2[i]);   // L2: atomics land in L2
            float d = obs2[i] - pv;
            g_p2[i] = 0.f;                 // restore for next call
            float v = block_reduce256(d * d, sh);
            if (t == 0) atomicAdd(&g_loss[2], (double)v);
        }
    }

    // --------- absolute last block writes the output ---------
    __syncthreads();
    if (t == 0) {
        __threadfence();
        int done = atomicAdd(&g_done, 1);
        if (done == MAIN_BLOCKS - 1) {
            __threadfence();
            double la = *(volatile double*)&g_loss[0];
            double lb = *(volatile double*)&g_loss[1];
            double lc = *(volatile double*)&g_loss[2];
            la /= (double)((size_t)NG * (size_t)C0);
            lb /= (double)RM;
            lc = 0.5 * lc / (double)C0;
            out[0] = (float)((la + lb + lc) / 3.0);
            g_loss[0] = 0.0; g_loss[1] = 0.0; g_loss[2] = 0.0;
            g_a_done = 0; g_p1_done = 0; g_fin = 0; g_done = 0;
        }
    }
}

extern "C" void kernel_launch(void* const* d_in, const int* in_sizes, int n_in,
                              void* d_out, int out_size) {
    const float* theta0   = (const float*)d_in[0];
    const float* theta1   = (const float*)d_in[1];
    const float* obs0     = (const float*)d_in[2];
    const float* obs1     = (const float*)d_in[3];
    const float* obs2     = (const float*)d_in[4];
    const void*  idx0     = d_in[5];
    const float* mapping1 = (const float*)d_in[6];
    float* out = (float*)d_out;

    k_all<<<MAIN_BLOCKS, 256>>>(theta0, obs0, theta1,
                                (const unsigned int*)idx0,
                                mapping1, obs1, obs2, out);
}